// round 16
// baseline (speedup 1.0000x reference)
#include <cuda_runtime.h>
#include <cuda_fp16.h>
#include <math.h>

#define SQ   2048
#define HDIM 4096
#define NH   32
#define DH   128
#define IDIM 11008

#define TM 128
#define TN 256
#define TK 64
#define STAGE_BYTES 49152          // A 16KB + B 32KB
#define GEMM_DSMEM (3 * STAGE_BYTES + 1024)

// flash smem: Q 4x16KB @0 ; 2 KV stages of 32KB (K 16KB | V 16KB)
#define FLASH_DSMEM (65536 + 2 * 32768 + 1024)

// ---------------- scratch (device globals; no allocation allowed) -----------
__device__ float g_qbuf[(size_t)SQ * HDIM];
__device__ float g_kbuf[(size_t)SQ * HDIM];
__device__ float g_hid2[(size_t)SQ * HDIM];
__device__ float g_gate[(size_t)SQ * IDIM];
__device__ float g_up  [(size_t)SQ * IDIM];
// fp16 activations (reused across all GEMMs, sized for the largest)
__device__ __half g_act[(size_t)SQ * IDIM];
// flash operands: split q, single k, transposed v ([nh,dh,S])
__device__ __half g_qhi[(size_t)NH * SQ * DH];
__device__ __half g_qlo[(size_t)NH * SQ * DH];
__device__ __half g_kh [(size_t)NH * SQ * DH];
__device__ __half g_vt [(size_t)NH * DH * SQ];
// fp16 transposed weights, stored [N, K]
__device__ __half g_wq[(size_t)HDIM * HDIM];
__device__ __half g_wk[(size_t)HDIM * HDIM];
__device__ __half g_wv[(size_t)HDIM * HDIM];
__device__ __half g_wo[(size_t)HDIM * HDIM];
__device__ __half g_wg[(size_t)IDIM * HDIM];
__device__ __half g_wu[(size_t)IDIM * HDIM];
__device__ __half g_wd[(size_t)HDIM * IDIM];

// ---------------- PTX helpers ------------------------------------------------
__device__ __forceinline__ unsigned smem_u32(const void* p) {
    unsigned a;
    asm("{ .reg .u64 t; cvta.to.shared.u64 t, %1; cvt.u32.u64 %0, t; }"
        : "=r"(a) : "l"(p));
    return a;
}
__device__ __forceinline__ unsigned swz(unsigned off) {
    return off ^ ((off >> 3) & 0x70);
}
__device__ __forceinline__ void cp16(unsigned dst, const void* src) {
    asm volatile("cp.async.cg.shared.global [%0], [%1], 16;" :: "r"(dst), "l"(src));
}
__device__ __forceinline__ void cp_commit() {
    asm volatile("cp.async.commit_group;" ::: "memory");
}
__device__ __forceinline__ void cp_wait(int n) {
    if (n == 0)      asm volatile("cp.async.wait_group 0;" ::: "memory");
    else             asm volatile("cp.async.wait_group 1;" ::: "memory");
}
__device__ __forceinline__ void ldsm_x4(unsigned r[4], unsigned addr) {
    asm volatile("ldmatrix.sync.aligned.m8n8.x4.shared.b16 {%0,%1,%2,%3}, [%4];"
                 : "=r"(r[0]), "=r"(r[1]), "=r"(r[2]), "=r"(r[3]) : "r"(addr));
}
__device__ __forceinline__ void mma_f16(float d[4], const unsigned a[4],
                                        const unsigned b[2]) {
    asm volatile(
        "mma.sync.aligned.m16n8k16.row.col.f32.f16.f16.f32 "
        "{%0,%1,%2,%3}, {%4,%5,%6,%7}, {%8,%9}, {%0,%1,%2,%3};"
        : "+f"(d[0]), "+f"(d[1]), "+f"(d[2]), "+f"(d[3])
        : "r"(a[0]), "r"(a[1]), "r"(a[2]), "r"(a[3]), "r"(b[0]), "r"(b[1]));
}
__device__ __forceinline__ unsigned pack_f16x2(float x, float y) {
    __half2 v = __floats2half2_rn(x, y);
    return *(unsigned*)&v;
}
__device__ __forceinline__ void split_f16(float x, __half& h, __half& l) {
    h = __float2half_rn(x);
    l = __float2half_rn(x - __half2float(h));
}

// ---------------- tensor-core GEMM: C[M,N] = A @ B^T (fp16) ------------------
// CTA tile 128x256, 8 warps in 2(M)x4(N), warp tile 64x64.
// A: [M,K] fp16, B: [N,K] fp16 (pre-transposed weights).
// EPI 0: plain fp32 store; 1: +residual; 2: [nh,S,dh] layout (head per elem).
// Stage layout: [A 16KB | B 32KB] (rows of 128B, SW128).
__device__ __forceinline__ void load_chunk(unsigned sb, int tid,
                                           const __half* a,
                                           const __half* b,
                                           size_t koff, int K) {
    const __half* ap = a + koff;
#pragma unroll
    for (int j = 0; j < 4; j++) {
        int idx = tid + j * 256;            // 0..1023 -> 128 rows x 8 segs
        int row = idx >> 3, c = idx & 7;
        cp16(sb + swz(row * 128 + c * 16), ap + (size_t)row * K + c * 8);
    }
    const __half* bp = b + koff;
#pragma unroll
    for (int j = 0; j < 8; j++) {
        int idx = tid + j * 256;            // 0..2047 -> 256 rows x 8 segs
        int row = idx >> 3, c = idx & 7;
        cp16(sb + 16384 + swz(row * 128 + c * 16), bp + (size_t)row * K + c * 8);
    }
    cp_commit();
}

template <int EPI>
__global__ void __launch_bounds__(256, 1) tngemm(
    const __half* __restrict__ A, const __half* __restrict__ B,
    float* __restrict__ C, const float* __restrict__ R, int K, int N) {
    extern __shared__ char dsm_raw[];
    int tid = threadIdx.x, wid = tid >> 5, lane = tid & 31;
    int brow = blockIdx.x * TM, bcol = blockIdx.y * TN;

    unsigned dsm = (smem_u32(dsm_raw) + 1023u) & ~1023u;

    int wm = wid & 1, wn = wid >> 1;        // 2(M) x 4(N) warp grid
    int r8 = lane & 7, mat = lane >> 3;
    unsigned arow_off = (unsigned)(wm * 64 + ((mat & 1) ? 8 : 0) + r8) * 128;
    unsigned brow_off = (unsigned)(wn * 64 + ((mat & 2) ? 8 : 0) + r8) * 128;
    unsigned achunk = (unsigned)(mat >> 1);
    unsigned bchunk = (unsigned)(mat & 1);

    const __half* a_p = A + (size_t)brow * K;
    const __half* b_p = B + (size_t)bcol * K;

    float acc[4][8][4];
#pragma unroll
    for (int ma = 0; ma < 4; ma++)
#pragma unroll
        for (int ng = 0; ng < 8; ng++)
#pragma unroll
            for (int c = 0; c < 4; c++) acc[ma][ng][c] = 0.f;

    int NC = K / TK;
    load_chunk(dsm + 0 * STAGE_BYTES, tid, a_p, b_p, 0, K);
    load_chunk(dsm + 1 * STAGE_BYTES, tid, a_p, b_p, TK, K);

    for (int i = 0; i < NC; i++) {
        cp_wait(i < NC - 1 ? 1 : 0);
        __syncthreads();
        if (i + 2 < NC)
            load_chunk(dsm + ((i + 2) % 3) * STAGE_BYTES, tid, a_p, b_p,
                       (size_t)(i + 2) * TK, K);

        unsigned sb = dsm + (i % 3) * STAGE_BYTES;
#pragma unroll
        for (int s = 0; s < 4; s++) {
            unsigned ka = (2 * s + achunk) * 16;
            unsigned kb = (2 * s + bchunk) * 16;
            unsigned ah[4][4], bf[8][2];
#pragma unroll
            for (int ma = 0; ma < 4; ma++)
                ldsm_x4(ah[ma], sb + swz(arow_off + ma * 2048 + ka));
#pragma unroll
            for (int nb = 0; nb < 4; nb++) {
                unsigned off = swz(brow_off + nb * 2048 + kb);
                unsigned t[4];
                ldsm_x4(t, sb + 16384 + off);
                bf[nb * 2][0] = t[0]; bf[nb * 2][1] = t[1];
                bf[nb * 2 + 1][0] = t[2]; bf[nb * 2 + 1][1] = t[3];
            }
#pragma unroll
            for (int ma = 0; ma < 4; ma++)
#pragma unroll
                for (int ng = 0; ng < 8; ng++)
                    mma_f16(acc[ma][ng], ah[ma], bf[ng]);
        }
    }

    int qd = lane >> 2, c2 = (lane & 3) * 2;
#pragma unroll
    for (int ma = 0; ma < 4; ma++) {
        int row0 = brow + wm * 64 + ma * 16 + qd;
#pragma unroll
        for (int ng = 0; ng < 8; ng++) {
            int colg = bcol + wn * 64 + ng * 8 + c2;
            float2 lo = {acc[ma][ng][0], acc[ma][ng][1]};
            float2 hi = {acc[ma][ng][2], acc[ma][ng][3]};
            if (EPI == 2) {
                int h = colg >> 7, d = colg & 127;
                float* d0 = C + ((size_t)h * SQ + row0) * DH + d;
                float* d1 = C + ((size_t)h * SQ + row0 + 8) * DH + d;
                *(float2*)d0 = lo;
                *(float2*)d1 = hi;
            } else {
                size_t b0 = (size_t)row0 * N + colg;
                size_t b1 = (size_t)(row0 + 8) * N + colg;
                if (EPI == 1) {
                    float2 r0 = *(const float2*)(R + b0);
                    float2 r1 = *(const float2*)(R + b1);
                    lo.x += r0.x; lo.y += r0.y;
                    hi.x += r1.x; hi.y += r1.y;
                }
                *(float2*)(C + b0) = lo;
                *(float2*)(C + b1) = hi;
            }
        }
    }
}

// ---------------- weight convert: W[K,N] fp32 -> fp16 [N,K] ------------------
// 64(K) x 32(N) tiles; half2 stores (128B per warp-row).
__global__ void convert_w(const float* __restrict__ W,
                          __half* __restrict__ out, int K, int N) {
    __shared__ float t[64][33];
    int tx = threadIdx.x, ty = threadIdx.y;   // (32, 8)
    int n0 = blockIdx.x * 32, k0 = blockIdx.y * 64;
#pragma unroll
    for (int j = 0; j < 8; j++)
        t[ty + j * 8][tx] = W[(size_t)(k0 + ty + j * 8) * N + n0 + tx];
    __syncthreads();
#pragma unroll
    for (int j = 0; j < 4; j++) {
        int n = ty + j * 8;
        __half2 v = __floats2half2_rn(t[2 * tx][n], t[2 * tx + 1][n]);
        *(__half2*)(out + (size_t)(n0 + n) * K + k0 + 2 * tx) = v;
    }
}

// ---------------- V transpose: [nh,S,dh] fp32 -> [nh,dh,S] fp16 --------------
__global__ void vtrans(const float* __restrict__ V, __half* __restrict__ vt) {
    __shared__ float t[32][33];
    int tx = threadIdx.x, ty = threadIdx.y;
    int s0 = blockIdx.x * 32, d0 = blockIdx.y * 32, h = blockIdx.z;
#pragma unroll
    for (int j = 0; j < 4; j++)
        t[ty + j * 8][tx] = V[((size_t)h * SQ + s0 + ty + j * 8) * DH + d0 + tx];
    __syncthreads();
#pragma unroll
    for (int j = 0; j < 4; j++)
        vt[((size_t)h * DH + d0 + ty + j * 8) * SQ + s0 + tx] =
            __float2half_rn(t[tx][ty + j * 8]);
}

// ---------------- RMSNorm -> fp16 --------------------------------------------
__global__ void __launch_bounds__(256) rmsnorm_f16(const float* __restrict__ x,
                                                   const float* __restrict__ w,
                                                   __half* __restrict__ out) {
    __shared__ float red[256];
    int row = blockIdx.x;
    int t = threadIdx.x;
    const float4* xr = (const float4*)(x + (size_t)row * HDIM);
    const float4* wr = (const float4*)w;
    float4 v[4];
    float ss = 0.f;
#pragma unroll
    for (int i = 0; i < 4; i++) {
        v[i] = xr[t + i * 256];
        ss += v[i].x * v[i].x + v[i].y * v[i].y + v[i].z * v[i].z + v[i].w * v[i].w;
    }
    red[t] = ss;
    __syncthreads();
    for (int s2 = 128; s2 > 0; s2 >>= 1) {
        if (t < s2) red[t] += red[t + s2];
        __syncthreads();
    }
    float inv = rsqrtf(red[0] / (float)HDIM + 1e-5f);
    __half2* orow = (__half2*)(out + (size_t)row * HDIM);
#pragma unroll
    for (int i = 0; i < 4; i++) {
        float4 ww = wr[t + i * 256];
        int b = (t + i * 256) * 2;
        orow[b]     = __floats2half2_rn(v[i].x * inv * ww.x, v[i].y * inv * ww.y);
        orow[b + 1] = __floats2half2_rn(v[i].z * inv * ww.z, v[i].w * inv * ww.w);
    }
}

// ---------------- RoPE + split: q split fp16, k single fp16; k fp32 out ------
__global__ void rope_split(const float* __restrict__ cosC,
                           const float* __restrict__ sinC,
                           const float* __restrict__ qin,
                           const float* __restrict__ kin,
                           __half* __restrict__ qhi,
                           __half* __restrict__ qlo,
                           __half* __restrict__ kh,
                           float* __restrict__ kout) {
    int s = blockIdx.x, h = blockIdx.y, j = threadIdx.x;  // 64 threads
    const float* cp = cosC + (size_t)s * DH;
    const float* sp = sinC + (size_t)s * DH;
    float c0 = cp[j], c1 = cp[j + 64], s0 = sp[j], s1 = sp[j + 64];
    size_t base = (size_t)s * HDIM + h * DH;
    float q0 = qin[base + j], q1 = qin[base + j + 64];
    float k0 = kin[base + j], k1 = kin[base + j + 64];
    float qr0 = q0 * c0 - q1 * s0, qr1 = q1 * c1 + q0 * s1;
    float kr0 = k0 * c0 - k1 * s0, kr1 = k1 * c1 + k0 * s1;
    size_t ob = ((size_t)h * SQ + s) * DH;
    kout[ob + j] = kr0;
    kout[ob + j + 64] = kr1;
    __half hh, ll;
    split_f16(qr0, hh, ll); qhi[ob + j] = hh;      qlo[ob + j] = ll;
    split_f16(qr1, hh, ll); qhi[ob + j + 64] = hh; qlo[ob + j + 64] = ll;
    kh[ob + j]      = __float2half_rn(kr0);
    kh[ob + j + 64] = __float2half_rn(kr1);
}

// ---------------- Flash attention (fp16 tensor cores) ------------------------
// BM=128 (8 warps x 16 rows), BN=64 keys, dh=128.
// smem: Q chunks [qhi c0|qhi c1|qlo c0|qlo c1] @ 0, 16KB each
//       KV stage s @ 65536+s*32768: k c0,c1 (8KB each) | vt c0,c1 (8KB each)
__global__ void __launch_bounds__(256) flash_tc(
    const __half* __restrict__ Qhi, const __half* __restrict__ Qlo,
    const __half* __restrict__ Kh, const __half* __restrict__ Vt,
    __half* __restrict__ O) {
    extern __shared__ char dsm_raw[];
    unsigned dsm = (smem_u32(dsm_raw) + 1023u) & ~1023u;
    int tid = threadIdx.x, wid = tid >> 5, lane = tid & 31;
    int h = blockIdx.y;
    int qb = gridDim.x - 1 - blockIdx.x;  // heavy blocks first
    int qbase = qb * 128;
    int r8 = lane & 7, mat = lane >> 3;
    int qd = lane >> 2, tig = lane & 3;

    // ---- load Q tile (once) ----
    const __half* qh_g = Qhi + ((size_t)h * SQ + qbase) * DH;
    const __half* ql_g = Qlo + ((size_t)h * SQ + qbase) * DH;
#pragma unroll
    for (int j = 0; j < 8; j++) {
        int idx = tid + j * 256;
        int row = idx >> 4, c8 = idx & 15;
        unsigned dst = dsm + ((c8 >> 3) * 16384) + swz(row * 128 + (c8 & 7) * 16);
        cp16(dst, qh_g + (size_t)row * DH + c8 * 8);
        cp16(dst + 32768, ql_g + (size_t)row * DH + c8 * 8);
    }
    cp_commit();

    const __half* kh_g = Kh + (size_t)h * SQ * DH;
    const __half* vt_g = Vt + (size_t)h * DH * SQ;
    int ntiles = 2 * qb + 2;

    auto load_kv = [&](int kt, int stg) {
        unsigned sb = dsm + 65536 + stg * 32768;
        const __half* kp = kh_g + (size_t)(kt * 64) * DH;
#pragma unroll
        for (int j = 0; j < 4; j++) {
            int idx = tid + j * 256;
            int row = idx >> 4, c8 = idx & 15;
            cp16(sb + ((c8 >> 3) * 8192) + swz(row * 128 + (c8 & 7) * 16),
                 kp + (size_t)row * DH + c8 * 8);
        }
        const __half* vp = vt_g + kt * 64;
#pragma unroll
        for (int j = 0; j < 4; j++) {
            int idx = tid + j * 256;
            int d = idx >> 3, c = idx & 7;
            cp16(sb + 16384 + ((d >> 6) * 8192) + swz((d & 63) * 128 + c * 16),
                 vp + (size_t)d * SQ + c * 8);
        }
        cp_commit();
    };

    float m0 = -1e30f, m1 = -1e30f, sum0 = 0.f, sum1 = 0.f;
    float acc[16][4];
#pragma unroll
    for (int n = 0; n < 16; n++)
#pragma unroll
        for (int c = 0; c < 4; c++) acc[n][c] = 0.f;

    unsigned aq_off = (unsigned)(wid * 16 + ((mat & 1) ? 8 : 0) + r8) * 128;
    unsigned ka_sel = (unsigned)(mat >> 1);
    unsigned kb_row = (unsigned)(((mat & 2) ? 8 : 0) + r8) * 128;
    unsigned kb_sel = (unsigned)(mat & 1);
    const float scale = 0.08838834764831845f;

    load_kv(0, 0);

    for (int kt = 0; kt < ntiles; kt++) {
        if (kt + 1 < ntiles) load_kv(kt + 1, (kt + 1) & 1);
        cp_wait(kt + 1 < ntiles ? 1 : 0);
        __syncthreads();
        unsigned sb = dsm + 65536 + (kt & 1) * 32768;

        // ---- QK^T (split-fp16 q, single fp16 k: 2 MMAs) ----
        float s[8][4];
#pragma unroll
        for (int j = 0; j < 8; j++)
#pragma unroll
            for (int c = 0; c < 4; c++) s[j][c] = 0.f;
#pragma unroll
        for (int ch = 0; ch < 2; ch++) {
#pragma unroll
            for (int ks = 0; ks < 4; ks++) {
                unsigned ah[4], al[4];
                unsigned aoff = swz(aq_off + (2 * ks + ka_sel) * 16);
                ldsm_x4(ah, dsm + ch * 16384 + aoff);
                ldsm_x4(al, dsm + 32768 + ch * 16384 + aoff);
                unsigned kb = (2 * ks + kb_sel) * 16;
#pragma unroll
                for (int nb = 0; nb < 4; nb++) {
                    unsigned boff = swz(kb_row + nb * 2048 + kb);
                    unsigned bh[4];
                    ldsm_x4(bh, sb + ch * 8192 + boff);
                    mma_f16(s[nb * 2], ah, bh);
                    mma_f16(s[nb * 2], al, bh);
                    mma_f16(s[nb * 2 + 1], ah, bh + 2);
                    mma_f16(s[nb * 2 + 1], al, bh + 2);
                }
            }
        }

        // ---- scale + causal mask ----
        int gr0 = qbase + wid * 16 + qd;
        bool diag = (kt * 64 + 63 > qbase + wid * 16);
#pragma unroll
        for (int j = 0; j < 8; j++) {
            int gc = kt * 64 + j * 8 + tig * 2;
#pragma unroll
            for (int c = 0; c < 4; c++) {
                float sv = s[j][c] * scale;
                if (diag) {
                    int gr = gr0 + ((c >= 2) ? 8 : 0);
                    if (gc + (c & 1) > gr) sv = -1e30f;
                }
                s[j][c] = sv;
            }
        }

        // ---- online softmax (rows qd / qd+8; 4 lanes per row) ----
        float rm0 = -1e30f, rm1 = -1e30f;
#pragma unroll
        for (int j = 0; j < 8; j++) {
            rm0 = fmaxf(rm0, fmaxf(s[j][0], s[j][1]));
            rm1 = fmaxf(rm1, fmaxf(s[j][2], s[j][3]));
        }
        rm0 = fmaxf(rm0, __shfl_xor_sync(0xffffffffu, rm0, 1));
        rm0 = fmaxf(rm0, __shfl_xor_sync(0xffffffffu, rm0, 2));
        rm1 = fmaxf(rm1, __shfl_xor_sync(0xffffffffu, rm1, 1));
        rm1 = fmaxf(rm1, __shfl_xor_sync(0xffffffffu, rm1, 2));
        float mn0 = fmaxf(m0, rm0), mn1 = fmaxf(m1, rm1);
        float co0 = __expf(m0 - mn0), co1 = __expf(m1 - mn1);
        m0 = mn0; m1 = mn1;
        float rs0 = 0.f, rs1 = 0.f;
#pragma unroll
        for (int j = 0; j < 8; j++) {
            s[j][0] = __expf(s[j][0] - mn0);
            s[j][1] = __expf(s[j][1] - mn0);
            s[j][2] = __expf(s[j][2] - mn1);
            s[j][3] = __expf(s[j][3] - mn1);
            rs0 += s[j][0] + s[j][1];
            rs1 += s[j][2] + s[j][3];
        }
        rs0 += __shfl_xor_sync(0xffffffffu, rs0, 1);
        rs0 += __shfl_xor_sync(0xffffffffu, rs0, 2);
        rs1 += __shfl_xor_sync(0xffffffffu, rs1, 1);
        rs1 += __shfl_xor_sync(0xffffffffu, rs1, 2);
        sum0 = sum0 * co0 + rs0;
        sum1 = sum1 * co1 + rs1;
#pragma unroll
        for (int n = 0; n < 16; n++) {
            acc[n][0] *= co0; acc[n][1] *= co0;
            acc[n][2] *= co1; acc[n][3] *= co1;
        }

        // ---- P @ V (fp16 P from C-frag reinterpretation; V^T as B operand) ----
#pragma unroll
        for (int t = 0; t < 4; t++) {
            unsigned pa[4];
            pa[0] = pack_f16x2(s[2 * t][0], s[2 * t][1]);
            pa[1] = pack_f16x2(s[2 * t][2], s[2 * t][3]);
            pa[2] = pack_f16x2(s[2 * t + 1][0], s[2 * t + 1][1]);
            pa[3] = pack_f16x2(s[2 * t + 1][2], s[2 * t + 1][3]);
            unsigned kbv = (2 * t + kb_sel) * 16;
#pragma unroll
            for (int nb = 0; nb < 8; nb++) {
                unsigned boff = swz(kb_row + (nb & 3) * 2048 + kbv);
                unsigned bv[4];
                ldsm_x4(bv, sb + 16384 + (nb >> 2) * 8192 + boff);
                mma_f16(acc[nb * 2], pa, bv);
                mma_f16(acc[nb * 2 + 1], pa, bv + 2);
            }
        }
        __syncthreads();
    }

    // ---- epilogue: O -> fp16 ----
    float i0 = 1.f / sum0, i1 = 1.f / sum1;
    int row0 = qbase + wid * 16 + qd;
    size_t b0 = (size_t)row0 * HDIM + (size_t)h * DH;
    size_t b1 = b0 + (size_t)8 * HDIM;
#pragma unroll
    for (int nb = 0; nb < 16; nb++) {
        int col = nb * 8 + tig * 2;
        *(__half2*)(O + b0 + col) =
            __floats2half2_rn(acc[nb][0] * i0, acc[nb][1] * i0);
        *(__half2*)(O + b1 + col) =
            __floats2half2_rn(acc[nb][2] * i1, acc[nb][3] * i1);
    }
}

// ---------------- SwiGLU -> fp16 ---------------------------------------------
__global__ void swiglu_f16(__half* __restrict__ out) {
    size_t i = (size_t)blockIdx.x * blockDim.x + threadIdx.x;
    size_t n = (size_t)SQ * IDIM / 4;
    if (i >= n) return;
    float4 g = ((const float4*)g_gate)[i];
    float4 u = ((const float4*)g_up)[i];
    float o0 = g.x / (1.f + __expf(-g.x)) * u.x;
    float o1 = g.y / (1.f + __expf(-g.y)) * u.y;
    float o2 = g.z / (1.f + __expf(-g.z)) * u.z;
    float o3 = g.w / (1.f + __expf(-g.w)) * u.w;
    ((__half2*)out)[i * 2]     = __floats2half2_rn(o0, o1);
    ((__half2*)out)[i * 2 + 1] = __floats2half2_rn(o2, o3);
}

// ---------------- host launcher ----------------------------------------------
extern "C" void kernel_launch(void* const* d_in, const int* in_sizes, int n_in,
                              void* d_out, int out_size) {
    const float* hidden = (const float*)d_in[0];
    // d_in[1] = position_ids (always arange(S); intentionally not dereferenced)
    const float* ln0    = (const float*)d_in[2];
    const float* ln1    = (const float*)d_in[3];
    const float* wq     = (const float*)d_in[4];
    const float* wk     = (const float*)d_in[5];
    const float* wv     = (const float*)d_in[6];
    const float* wo     = (const float*)d_in[7];
    const float* w_gate = (const float*)d_in[8];
    const float* w_up   = (const float*)d_in[9];
    const float* w_down = (const float*)d_in[10];
    const float* cosC   = (const float*)d_in[11];
    const float* sinC   = (const float*)d_in[12];

    float* out_h = (float*)d_out;
    float* out_k = out_h + (size_t)SQ * HDIM;
    float* out_v = out_k + (size_t)NH * SQ * DH;

    float *p_qbuf, *p_kbuf, *p_hid2, *p_gate, *p_up;
    __half *p_act, *p_qhi, *p_qlo, *p_kh, *p_vt;
    __half *p_wq, *p_wk, *p_wv, *p_wo, *p_wg, *p_wu, *p_wd;
    cudaGetSymbolAddress((void**)&p_qbuf, g_qbuf);
    cudaGetSymbolAddress((void**)&p_kbuf, g_kbuf);
    cudaGetSymbolAddress((void**)&p_hid2, g_hid2);
    cudaGetSymbolAddress((void**)&p_gate, g_gate);
    cudaGetSymbolAddress((void**)&p_up, g_up);
    cudaGetSymbolAddress((void**)&p_act, g_act);
    cudaGetSymbolAddress((void**)&p_qhi, g_qhi);
    cudaGetSymbolAddress((void**)&p_qlo, g_qlo);
    cudaGetSymbolAddress((void**)&p_kh, g_kh);
    cudaGetSymbolAddress((void**)&p_vt, g_vt);
    cudaGetSymbolAddress((void**)&p_wq, g_wq);
    cudaGetSymbolAddress((void**)&p_wk, g_wk);
    cudaGetSymbolAddress((void**)&p_wv, g_wv);
    cudaGetSymbolAddress((void**)&p_wo, g_wo);
    cudaGetSymbolAddress((void**)&p_wg, g_wg);
    cudaGetSymbolAddress((void**)&p_wu, g_wu);
    cudaGetSymbolAddress((void**)&p_wd, g_wd);

    cudaFuncSetAttribute(flash_tc, cudaFuncAttributeMaxDynamicSharedMemorySize,
                         FLASH_DSMEM);
    cudaFuncSetAttribute(tngemm<0>, cudaFuncAttributeMaxDynamicSharedMemorySize,
                         GEMM_DSMEM);
    cudaFuncSetAttribute(tngemm<1>, cudaFuncAttributeMaxDynamicSharedMemorySize,
                         GEMM_DSMEM);
    cudaFuncSetAttribute(tngemm<2>, cudaFuncAttributeMaxDynamicSharedMemorySize,
                         GEMM_DSMEM);

    dim3 cb(32, 8);
    // convert grids: (N/32, K/64)
    convert_w<<<dim3(HDIM / 32, HDIM / 64), cb>>>(wq, p_wq, HDIM, HDIM);
    convert_w<<<dim3(HDIM / 32, HDIM / 64), cb>>>(wk, p_wk, HDIM, HDIM);
    convert_w<<<dim3(HDIM / 32, HDIM / 64), cb>>>(wv, p_wv, HDIM, HDIM);
    convert_w<<<dim3(HDIM / 32, HDIM / 64), cb>>>(wo, p_wo, HDIM, HDIM);
    convert_w<<<dim3(IDIM / 32, HDIM / 64), cb>>>(w_gate, p_wg, HDIM, IDIM);
    convert_w<<<dim3(IDIM / 32, HDIM / 64), cb>>>(w_up, p_wu, HDIM, IDIM);
    convert_w<<<dim3(HDIM / 32, IDIM / 64), cb>>>(w_down, p_wd, IDIM, HDIM);

    dim3 gH(SQ / TM, HDIM / TN);   // (16, 16)
    dim3 gI(SQ / TM, IDIM / TN);   // (16, 43)

    // 1. pre-attn RMSNorm -> fp16
    rmsnorm_f16<<<SQ, 256>>>(hidden, ln0, p_act);
    // 2. QKV projections
    tngemm<0><<<gH, 256, GEMM_DSMEM>>>(p_act, p_wq, p_qbuf, nullptr, HDIM, HDIM);
    tngemm<0><<<gH, 256, GEMM_DSMEM>>>(p_act, p_wk, p_kbuf, nullptr, HDIM, HDIM);
    tngemm<2><<<gH, 256, GEMM_DSMEM>>>(p_act, p_wv, out_v, nullptr, HDIM, HDIM);
    // 3. RoPE -> fp16 q (split) / k (single) + fp32 k output; V transpose
    rope_split<<<dim3(SQ, NH), 64>>>(cosC, sinC, p_qbuf, p_kbuf,
                                     p_qhi, p_qlo, p_kh, out_k);
    vtrans<<<dim3(SQ / 32, DH / 32, NH), cb>>>(out_v, p_vt);
    // 4. causal flash attention (fp16 tensor cores) -> fp16 act
    flash_tc<<<dim3(SQ / 128, NH), 256, FLASH_DSMEM>>>(p_qhi, p_qlo, p_kh, p_vt,
                                                       p_act);
    // 5. output projection + residual
    tngemm<1><<<gH, 256, GEMM_DSMEM>>>(p_act, p_wo, p_hid2, hidden, HDIM, HDIM);
    // 6. post-attn RMSNorm -> fp16
    rmsnorm_f16<<<SQ, 256>>>(p_hid2, ln1, p_act);
    // 7. MLP gate / up
    tngemm<0><<<gI, 256, GEMM_DSMEM>>>(p_act, p_wg, p_gate, nullptr, HDIM, IDIM);
    tngemm<0><<<gI, 256, GEMM_DSMEM>>>(p_act, p_wu, p_up, nullptr, HDIM, IDIM);
    // 8. SwiGLU -> fp16
    swiglu_f16<<<(int)(((size_t)SQ * IDIM / 4 + 255) / 256), 256>>>(p_act);
    // 9. down projection + residual -> hidden output
    tngemm<1><<<gH, 256, GEMM_DSMEM>>>(p_act, p_wd, out_h, p_hid2, IDIM, HDIM);
}

// round 17
// speedup vs baseline: 1.0551x; 1.0551x over previous
#include <cuda_runtime.h>
#include <cuda_fp16.h>
#include <math.h>

#define SQ   2048
#define HDIM 4096
#define NH   32
#define DH   128
#define IDIM 11008

#define TM 128
#define TN 128
#define TK 64
#define STAGE_BYTES 32768          // 2 tiles (A|B) * 16KB
#define GEMM_DSMEM (3 * STAGE_BYTES + 1024)

// flash smem: Q 4x16KB @0 ; 2 KV stages of 32KB (K 16KB | V 16KB)
#define FLASH_DSMEM (65536 + 2 * 32768 + 1024)

// ---------------- scratch (device globals; no allocation allowed) -----------
__device__ float g_qbuf[(size_t)SQ * HDIM];
__device__ float g_kbuf[(size_t)SQ * HDIM];
__device__ float g_hid2[(size_t)SQ * HDIM];
__device__ float g_gate[(size_t)SQ * IDIM];
__device__ float g_up  [(size_t)SQ * IDIM];
// fp16 activations (reused across all GEMMs, sized for the largest)
__device__ __half g_act[(size_t)SQ * IDIM];
// flash operands: split q, single k, transposed v ([nh,dh,S])
__device__ __half g_qhi[(size_t)NH * SQ * DH];
__device__ __half g_qlo[(size_t)NH * SQ * DH];
__device__ __half g_kh [(size_t)NH * SQ * DH];
__device__ __half g_vt [(size_t)NH * DH * SQ];
// fp16 transposed weights, stored [N, K]
__device__ __half g_wq[(size_t)HDIM * HDIM];
__device__ __half g_wk[(size_t)HDIM * HDIM];
__device__ __half g_wv[(size_t)HDIM * HDIM];
__device__ __half g_wo[(size_t)HDIM * HDIM];
__device__ __half g_wg[(size_t)IDIM * HDIM];
__device__ __half g_wu[(size_t)IDIM * HDIM];
__device__ __half g_wd[(size_t)HDIM * IDIM];

// ---------------- PTX helpers ------------------------------------------------
__device__ __forceinline__ unsigned smem_u32(const void* p) {
    unsigned a;
    asm("{ .reg .u64 t; cvta.to.shared.u64 t, %1; cvt.u32.u64 %0, t; }"
        : "=r"(a) : "l"(p));
    return a;
}
__device__ __forceinline__ unsigned swz(unsigned off) {
    return off ^ ((off >> 3) & 0x70);
}
__device__ __forceinline__ void cp16(unsigned dst, const void* src) {
    asm volatile("cp.async.cg.shared.global [%0], [%1], 16;" :: "r"(dst), "l"(src));
}
__device__ __forceinline__ void cp_commit() {
    asm volatile("cp.async.commit_group;" ::: "memory");
}
__device__ __forceinline__ void cp_wait(int n) {
    if (n == 0)      asm volatile("cp.async.wait_group 0;" ::: "memory");
    else             asm volatile("cp.async.wait_group 1;" ::: "memory");
}
__device__ __forceinline__ void ldsm_x4(unsigned r[4], unsigned addr) {
    asm volatile("ldmatrix.sync.aligned.m8n8.x4.shared.b16 {%0,%1,%2,%3}, [%4];"
                 : "=r"(r[0]), "=r"(r[1]), "=r"(r[2]), "=r"(r[3]) : "r"(addr));
}
__device__ __forceinline__ void mma_f16(float d[4], const unsigned a[4],
                                        const unsigned b[2]) {
    asm volatile(
        "mma.sync.aligned.m16n8k16.row.col.f32.f16.f16.f32 "
        "{%0,%1,%2,%3}, {%4,%5,%6,%7}, {%8,%9}, {%0,%1,%2,%3};"
        : "+f"(d[0]), "+f"(d[1]), "+f"(d[2]), "+f"(d[3])
        : "r"(a[0]), "r"(a[1]), "r"(a[2]), "r"(a[3]), "r"(b[0]), "r"(b[1]));
}
__device__ __forceinline__ unsigned pack_f16x2(float x, float y) {
    __half2 v = __floats2half2_rn(x, y);
    return *(unsigned*)&v;
}
__device__ __forceinline__ void split_f16(float x, __half& h, __half& l) {
    h = __float2half_rn(x);
    l = __float2half_rn(x - __half2float(h));
}

// ---------------- tensor-core GEMM: C[M,N] = A @ B^T (fp16) ------------------
// CTA tile 128x128, 8 warps in 4(M)x2(N), warp tile 32x64 (R15-proven).
// A: [M,K] fp16, B: [N,K] fp16 (pre-transposed weights).
// EPI 0: plain fp32 store; 1: +residual; 2: [nh,S,dh] layout.
// Stage layout: [A | B] at 16KB offsets (128 rows x 128B, SW128).
__device__ __forceinline__ void load_chunk(unsigned sb, int tid,
                                           const __half* a,
                                           const __half* b,
                                           size_t koff, int K) {
    const __half* bases[2] = {a + koff, b + koff};
#pragma unroll
    for (int t2 = 0; t2 < 2; t2++) {
        const __half* bp = bases[t2];
        unsigned tb = sb + t2 * 16384;
#pragma unroll
        for (int j = 0; j < 4; j++) {
            int idx = tid + j * 256;
            int row = idx >> 3, c = idx & 7;
            cp16(tb + swz(row * 128 + c * 16), bp + (size_t)row * K + c * 8);
        }
    }
    cp_commit();
}

template <int EPI>
__global__ void __launch_bounds__(256) tngemm(
    const __half* __restrict__ A, const __half* __restrict__ B,
    float* __restrict__ C, const float* __restrict__ R, int K, int N) {
    extern __shared__ char dsm_raw[];
    int tid = threadIdx.x, wid = tid >> 5, lane = tid & 31;
    int brow = blockIdx.x * TM, bcol = blockIdx.y * TN;

    unsigned dsm = (smem_u32(dsm_raw) + 1023u) & ~1023u;

    int wm = wid & 3, wn = wid >> 2;        // 4(M) x 2(N) warp grid
    int r8 = lane & 7, mat = lane >> 3;
    unsigned arow_off = (unsigned)(wm * 32 + ((mat & 1) ? 8 : 0) + r8) * 128;
    unsigned brow_off = (unsigned)(wn * 64 + ((mat & 2) ? 8 : 0) + r8) * 128;
    unsigned achunk = (unsigned)(mat >> 1);
    unsigned bchunk = (unsigned)(mat & 1);

    const __half* a_p = A + (size_t)brow * K;
    const __half* b_p = B + (size_t)bcol * K;

    float acc[2][8][4];
#pragma unroll
    for (int ma = 0; ma < 2; ma++)
#pragma unroll
        for (int ng = 0; ng < 8; ng++)
#pragma unroll
            for (int c = 0; c < 4; c++) acc[ma][ng][c] = 0.f;

    int NC = K / TK;
    load_chunk(dsm + 0 * STAGE_BYTES, tid, a_p, b_p, 0, K);
    load_chunk(dsm + 1 * STAGE_BYTES, tid, a_p, b_p, TK, K);

    for (int i = 0; i < NC; i++) {
        cp_wait(i < NC - 1 ? 1 : 0);
        __syncthreads();
        if (i + 2 < NC)
            load_chunk(dsm + ((i + 2) % 3) * STAGE_BYTES, tid, a_p, b_p,
                       (size_t)(i + 2) * TK, K);

        unsigned sb = dsm + (i % 3) * STAGE_BYTES;
#pragma unroll
        for (int s = 0; s < 4; s++) {
            unsigned ka = (2 * s + achunk) * 16;
            unsigned kb = (2 * s + bchunk) * 16;
            unsigned ah[2][4], bf[8][2];
#pragma unroll
            for (int ma = 0; ma < 2; ma++)
                ldsm_x4(ah[ma], sb + swz(arow_off + ma * 2048 + ka));
#pragma unroll
            for (int nb = 0; nb < 4; nb++) {
                unsigned off = swz(brow_off + nb * 2048 + kb);
                unsigned t[4];
                ldsm_x4(t, sb + 16384 + off);
                bf[nb * 2][0] = t[0]; bf[nb * 2][1] = t[1];
                bf[nb * 2 + 1][0] = t[2]; bf[nb * 2 + 1][1] = t[3];
            }
#pragma unroll
            for (int ma = 0; ma < 2; ma++)
#pragma unroll
                for (int ng = 0; ng < 8; ng++)
                    mma_f16(acc[ma][ng], ah[ma], bf[ng]);
        }
    }

    int qd = lane >> 2, c2 = (lane & 3) * 2;
#pragma unroll
    for (int ma = 0; ma < 2; ma++) {
        int row0 = brow + wm * 32 + ma * 16 + qd;
#pragma unroll
        for (int ng = 0; ng < 8; ng++) {
            int colw = wn * 64 + ng * 8 + c2;
            float2 lo = {acc[ma][ng][0], acc[ma][ng][1]};
            float2 hi = {acc[ma][ng][2], acc[ma][ng][3]};
            if (EPI == 2) {
                int h = bcol >> 7;   // TN==128: whole tile in one head
                float* d0 = C + ((size_t)h * SQ + row0) * DH + colw;
                float* d1 = C + ((size_t)h * SQ + row0 + 8) * DH + colw;
                *(float2*)d0 = lo;
                *(float2*)d1 = hi;
            } else {
                size_t b0 = (size_t)row0 * N + bcol + colw;
                size_t b1 = (size_t)(row0 + 8) * N + bcol + colw;
                if (EPI == 1) {
                    float2 r0 = *(const float2*)(R + b0);
                    float2 r1 = *(const float2*)(R + b1);
                    lo.x += r0.x; lo.y += r0.y;
                    hi.x += r1.x; hi.y += r1.y;
                }
                *(float2*)(C + b0) = lo;
                *(float2*)(C + b1) = hi;
            }
        }
    }
}

// ---------------- weight convert: W[K,N] fp32 -> fp16 [N,K] ------------------
// 64(K) x 32(N) tiles; half2 stores (128B per warp-row). (R16-proven, faster)
__global__ void convert_w(const float* __restrict__ W,
                          __half* __restrict__ out, int K, int N) {
    __shared__ float t[64][33];
    int tx = threadIdx.x, ty = threadIdx.y;   // (32, 8)
    int n0 = blockIdx.x * 32, k0 = blockIdx.y * 64;
#pragma unroll
    for (int j = 0; j < 8; j++)
        t[ty + j * 8][tx] = W[(size_t)(k0 + ty + j * 8) * N + n0 + tx];
    __syncthreads();
#pragma unroll
    for (int j = 0; j < 4; j++) {
        int n = ty + j * 8;
        __half2 v = __floats2half2_rn(t[2 * tx][n], t[2 * tx + 1][n]);
        *(__half2*)(out + (size_t)(n0 + n) * K + k0 + 2 * tx) = v;
    }
}

// ---------------- V transpose: [nh,S,dh] fp32 -> [nh,dh,S] fp16 --------------
__global__ void vtrans(const float* __restrict__ V, __half* __restrict__ vt) {
    __shared__ float t[32][33];
    int tx = threadIdx.x, ty = threadIdx.y;
    int s0 = blockIdx.x * 32, d0 = blockIdx.y * 32, h = blockIdx.z;
#pragma unroll
    for (int j = 0; j < 4; j++)
        t[ty + j * 8][tx] = V[((size_t)h * SQ + s0 + ty + j * 8) * DH + d0 + tx];
    __syncthreads();
#pragma unroll
    for (int j = 0; j < 4; j++)
        vt[((size_t)h * DH + d0 + ty + j * 8) * SQ + s0 + tx] =
            __float2half_rn(t[tx][ty + j * 8]);
}

// ---------------- RMSNorm -> fp16 --------------------------------------------
__global__ void __launch_bounds__(256) rmsnorm_f16(const float* __restrict__ x,
                                                   const float* __restrict__ w,
                                                   __half* __restrict__ out) {
    __shared__ float red[256];
    int row = blockIdx.x;
    int t = threadIdx.x;
    const float4* xr = (const float4*)(x + (size_t)row * HDIM);
    const float4* wr = (const float4*)w;
    float4 v[4];
    float ss = 0.f;
#pragma unroll
    for (int i = 0; i < 4; i++) {
        v[i] = xr[t + i * 256];
        ss += v[i].x * v[i].x + v[i].y * v[i].y + v[i].z * v[i].z + v[i].w * v[i].w;
    }
    red[t] = ss;
    __syncthreads();
    for (int s2 = 128; s2 > 0; s2 >>= 1) {
        if (t < s2) red[t] += red[t + s2];
        __syncthreads();
    }
    float inv = rsqrtf(red[0] / (float)HDIM + 1e-5f);
    __half2* orow = (__half2*)(out + (size_t)row * HDIM);
#pragma unroll
    for (int i = 0; i < 4; i++) {
        float4 ww = wr[t + i * 256];
        int b = (t + i * 256) * 2;
        orow[b]     = __floats2half2_rn(v[i].x * inv * ww.x, v[i].y * inv * ww.y);
        orow[b + 1] = __floats2half2_rn(v[i].z * inv * ww.z, v[i].w * inv * ww.w);
    }
}

// ---------------- RoPE + split: q split fp16, k single fp16; k fp32 out ------
__global__ void rope_split(const float* __restrict__ cosC,
                           const float* __restrict__ sinC,
                           const float* __restrict__ qin,
                           const float* __restrict__ kin,
                           __half* __restrict__ qhi,
                           __half* __restrict__ qlo,
                           __half* __restrict__ kh,
                           float* __restrict__ kout) {
    int s = blockIdx.x, h = blockIdx.y, j = threadIdx.x;  // 64 threads
    const float* cp = cosC + (size_t)s * DH;
    const float* sp = sinC + (size_t)s * DH;
    float c0 = cp[j], c1 = cp[j + 64], s0 = sp[j], s1 = sp[j + 64];
    size_t base = (size_t)s * HDIM + h * DH;
    float q0 = qin[base + j], q1 = qin[base + j + 64];
    float k0 = kin[base + j], k1 = kin[base + j + 64];
    float qr0 = q0 * c0 - q1 * s0, qr1 = q1 * c1 + q0 * s1;
    float kr0 = k0 * c0 - k1 * s0, kr1 = k1 * c1 + k0 * s1;
    size_t ob = ((size_t)h * SQ + s) * DH;
    kout[ob + j] = kr0;
    kout[ob + j + 64] = kr1;
    __half hh, ll;
    split_f16(qr0, hh, ll); qhi[ob + j] = hh;      qlo[ob + j] = ll;
    split_f16(qr1, hh, ll); qhi[ob + j + 64] = hh; qlo[ob + j + 64] = ll;
    kh[ob + j]      = __float2half_rn(kr0);
    kh[ob + j + 64] = __float2half_rn(kr1);
}

// ---------------- Flash attention (fp16 tensor cores) ------------------------
// BM=128 (8 warps x 16 rows), BN=64 keys, dh=128.
// smem: Q chunks [qhi c0|qhi c1|qlo c0|qlo c1] @ 0, 16KB each
//       KV stage s @ 65536+s*32768: k c0,c1 (8KB each) | vt c0,c1 (8KB each)
__global__ void __launch_bounds__(256) flash_tc(
    const __half* __restrict__ Qhi, const __half* __restrict__ Qlo,
    const __half* __restrict__ Kh, const __half* __restrict__ Vt,
    __half* __restrict__ O) {
    extern __shared__ char dsm_raw[];
    unsigned dsm = (smem_u32(dsm_raw) + 1023u) & ~1023u;
    int tid = threadIdx.x, wid = tid >> 5, lane = tid & 31;
    int h = blockIdx.y;
    int qb = gridDim.x - 1 - blockIdx.x;  // heavy blocks first
    int qbase = qb * 128;
    int r8 = lane & 7, mat = lane >> 3;
    int qd = lane >> 2, tig = lane & 3;

    // ---- load Q tile (once) ----
    const __half* qh_g = Qhi + ((size_t)h * SQ + qbase) * DH;
    const __half* ql_g = Qlo + ((size_t)h * SQ + qbase) * DH;
#pragma unroll
    for (int j = 0; j < 8; j++) {
        int idx = tid + j * 256;
        int row = idx >> 4, c8 = idx & 15;
        unsigned dst = dsm + ((c8 >> 3) * 16384) + swz(row * 128 + (c8 & 7) * 16);
        cp16(dst, qh_g + (size_t)row * DH + c8 * 8);
        cp16(dst + 32768, ql_g + (size_t)row * DH + c8 * 8);
    }
    cp_commit();

    const __half* kh_g = Kh + (size_t)h * SQ * DH;
    const __half* vt_g = Vt + (size_t)h * DH * SQ;
    int ntiles = 2 * qb + 2;

    auto load_kv = [&](int kt, int stg) {
        unsigned sb = dsm + 65536 + stg * 32768;
        const __half* kp = kh_g + (size_t)(kt * 64) * DH;
#pragma unroll
        for (int j = 0; j < 4; j++) {
            int idx = tid + j * 256;
            int row = idx >> 4, c8 = idx & 15;
            cp16(sb + ((c8 >> 3) * 8192) + swz(row * 128 + (c8 & 7) * 16),
                 kp + (size_t)row * DH + c8 * 8);
        }
        const __half* vp = vt_g + kt * 64;
#pragma unroll
        for (int j = 0; j < 4; j++) {
            int idx = tid + j * 256;
            int d = idx >> 3, c = idx & 7;
            cp16(sb + 16384 + ((d >> 6) * 8192) + swz((d & 63) * 128 + c * 16),
                 vp + (size_t)d * SQ + c * 8);
        }
        cp_commit();
    };

    float m0 = -1e30f, m1 = -1e30f, sum0 = 0.f, sum1 = 0.f;
    float acc[16][4];
#pragma unroll
    for (int n = 0; n < 16; n++)
#pragma unroll
        for (int c = 0; c < 4; c++) acc[n][c] = 0.f;

    unsigned aq_off = (unsigned)(wid * 16 + ((mat & 1) ? 8 : 0) + r8) * 128;
    unsigned ka_sel = (unsigned)(mat >> 1);
    unsigned kb_row = (unsigned)(((mat & 2) ? 8 : 0) + r8) * 128;
    unsigned kb_sel = (unsigned)(mat & 1);
    const float scale = 0.08838834764831845f;

    load_kv(0, 0);

    for (int kt = 0; kt < ntiles; kt++) {
        if (kt + 1 < ntiles) load_kv(kt + 1, (kt + 1) & 1);
        cp_wait(kt + 1 < ntiles ? 1 : 0);
        __syncthreads();
        unsigned sb = dsm + 65536 + (kt & 1) * 32768;

        // ---- QK^T (split-fp16 q, single fp16 k: 2 MMAs) ----
        float s[8][4];
#pragma unroll
        for (int j = 0; j < 8; j++)
#pragma unroll
            for (int c = 0; c < 4; c++) s[j][c] = 0.f;
#pragma unroll
        for (int ch = 0; ch < 2; ch++) {
#pragma unroll
            for (int ks = 0; ks < 4; ks++) {
                unsigned ah[4], al[4];
                unsigned aoff = swz(aq_off + (2 * ks + ka_sel) * 16);
                ldsm_x4(ah, dsm + ch * 16384 + aoff);
                ldsm_x4(al, dsm + 32768 + ch * 16384 + aoff);
                unsigned kb = (2 * ks + kb_sel) * 16;
#pragma unroll
                for (int nb = 0; nb < 4; nb++) {
                    unsigned boff = swz(kb_row + nb * 2048 + kb);
                    unsigned bh[4];
                    ldsm_x4(bh, sb + ch * 8192 + boff);
                    mma_f16(s[nb * 2], ah, bh);
                    mma_f16(s[nb * 2], al, bh);
                    mma_f16(s[nb * 2 + 1], ah, bh + 2);
                    mma_f16(s[nb * 2 + 1], al, bh + 2);
                }
            }
        }

        // ---- scale + causal mask ----
        int gr0 = qbase + wid * 16 + qd;
        bool diag = (kt * 64 + 63 > qbase + wid * 16);
#pragma unroll
        for (int j = 0; j < 8; j++) {
            int gc = kt * 64 + j * 8 + tig * 2;
#pragma unroll
            for (int c = 0; c < 4; c++) {
                float sv = s[j][c] * scale;
                if (diag) {
                    int gr = gr0 + ((c >= 2) ? 8 : 0);
                    if (gc + (c & 1) > gr) sv = -1e30f;
                }
                s[j][c] = sv;
            }
        }

        // ---- online softmax (rows qd / qd+8; 4 lanes per row) ----
        float rm0 = -1e30f, rm1 = -1e30f;
#pragma unroll
        for (int j = 0; j < 8; j++) {
            rm0 = fmaxf(rm0, fmaxf(s[j][0], s[j][1]));
            rm1 = fmaxf(rm1, fmaxf(s[j][2], s[j][3]));
        }
        rm0 = fmaxf(rm0, __shfl_xor_sync(0xffffffffu, rm0, 1));
        rm0 = fmaxf(rm0, __shfl_xor_sync(0xffffffffu, rm0, 2));
        rm1 = fmaxf(rm1, __shfl_xor_sync(0xffffffffu, rm1, 1));
        rm1 = fmaxf(rm1, __shfl_xor_sync(0xffffffffu, rm1, 2));
        float mn0 = fmaxf(m0, rm0), mn1 = fmaxf(m1, rm1);
        float co0 = __expf(m0 - mn0), co1 = __expf(m1 - mn1);
        m0 = mn0; m1 = mn1;
        float rs0 = 0.f, rs1 = 0.f;
#pragma unroll
        for (int j = 0; j < 8; j++) {
            s[j][0] = __expf(s[j][0] - mn0);
            s[j][1] = __expf(s[j][1] - mn0);
            s[j][2] = __expf(s[j][2] - mn1);
            s[j][3] = __expf(s[j][3] - mn1);
            rs0 += s[j][0] + s[j][1];
            rs1 += s[j][2] + s[j][3];
        }
        rs0 += __shfl_xor_sync(0xffffffffu, rs0, 1);
        rs0 += __shfl_xor_sync(0xffffffffu, rs0, 2);
        rs1 += __shfl_xor_sync(0xffffffffu, rs1, 1);
        rs1 += __shfl_xor_sync(0xffffffffu, rs1, 2);
        sum0 = sum0 * co0 + rs0;
        sum1 = sum1 * co1 + rs1;
#pragma unroll
        for (int n = 0; n < 16; n++) {
            acc[n][0] *= co0; acc[n][1] *= co0;
            acc[n][2] *= co1; acc[n][3] *= co1;
        }

        // ---- P @ V (fp16 P from C-frag reinterpretation; V^T as B operand) ----
#pragma unroll
        for (int t = 0; t < 4; t++) {
            unsigned pa[4];
            pa[0] = pack_f16x2(s[2 * t][0], s[2 * t][1]);
            pa[1] = pack_f16x2(s[2 * t][2], s[2 * t][3]);
            pa[2] = pack_f16x2(s[2 * t + 1][0], s[2 * t + 1][1]);
            pa[3] = pack_f16x2(s[2 * t + 1][2], s[2 * t + 1][3]);
            unsigned kbv = (2 * t + kb_sel) * 16;
#pragma unroll
            for (int nb = 0; nb < 8; nb++) {
                unsigned boff = swz(kb_row + (nb & 3) * 2048 + kbv);
                unsigned bv[4];
                ldsm_x4(bv, sb + 16384 + (nb >> 2) * 8192 + boff);
                mma_f16(acc[nb * 2], pa, bv);
                mma_f16(acc[nb * 2 + 1], pa, bv + 2);
            }
        }
        __syncthreads();
    }

    // ---- epilogue: O -> fp16 ----
    float i0 = 1.f / sum0, i1 = 1.f / sum1;
    int row0 = qbase + wid * 16 + qd;
    size_t b0 = (size_t)row0 * HDIM + (size_t)h * DH;
    size_t b1 = b0 + (size_t)8 * HDIM;
#pragma unroll
    for (int nb = 0; nb < 16; nb++) {
        int col = nb * 8 + tig * 2;
        *(__half2*)(O + b0 + col) =
            __floats2half2_rn(acc[nb][0] * i0, acc[nb][1] * i0);
        *(__half2*)(O + b1 + col) =
            __floats2half2_rn(acc[nb][2] * i1, acc[nb][3] * i1);
    }
}

// ---------------- SwiGLU -> fp16 ---------------------------------------------
__global__ void swiglu_f16(__half* __restrict__ out) {
    size_t i = (size_t)blockIdx.x * blockDim.x + threadIdx.x;
    size_t n = (size_t)SQ * IDIM / 4;
    if (i >= n) return;
    float4 g = ((const float4*)g_gate)[i];
    float4 u = ((const float4*)g_up)[i];
    float o0 = g.x / (1.f + __expf(-g.x)) * u.x;
    float o1 = g.y / (1.f + __expf(-g.y)) * u.y;
    float o2 = g.z / (1.f + __expf(-g.z)) * u.z;
    float o3 = g.w / (1.f + __expf(-g.w)) * u.w;
    ((__half2*)out)[i * 2]     = __floats2half2_rn(o0, o1);
    ((__half2*)out)[i * 2 + 1] = __floats2half2_rn(o2, o3);
}

// ---------------- host launcher ----------------------------------------------
extern "C" void kernel_launch(void* const* d_in, const int* in_sizes, int n_in,
                              void* d_out, int out_size) {
    const float* hidden = (const float*)d_in[0];
    // d_in[1] = position_ids (always arange(S); intentionally not dereferenced)
    const float* ln0    = (const float*)d_in[2];
    const float* ln1    = (const float*)d_in[3];
    const float* wq     = (const float*)d_in[4];
    const float* wk     = (const float*)d_in[5];
    const float* wv     = (const float*)d_in[6];
    const float* wo     = (const float*)d_in[7];
    const float* w_gate = (const float*)d_in[8];
    const float* w_up   = (const float*)d_in[9];
    const float* w_down = (const float*)d_in[10];
    const float* cosC   = (const float*)d_in[11];
    const float* sinC   = (const float*)d_in[12];

    float* out_h = (float*)d_out;
    float* out_k = out_h + (size_t)SQ * HDIM;
    float* out_v = out_k + (size_t)NH * SQ * DH;

    float *p_qbuf, *p_kbuf, *p_hid2, *p_gate, *p_up;
    __half *p_act, *p_qhi, *p_qlo, *p_kh, *p_vt;
    __half *p_wq, *p_wk, *p_wv, *p_wo, *p_wg, *p_wu, *p_wd;
    cudaGetSymbolAddress((void**)&p_qbuf, g_qbuf);
    cudaGetSymbolAddress((void**)&p_kbuf, g_kbuf);
    cudaGetSymbolAddress((void**)&p_hid2, g_hid2);
    cudaGetSymbolAddress((void**)&p_gate, g_gate);
    cudaGetSymbolAddress((void**)&p_up, g_up);
    cudaGetSymbolAddress((void**)&p_act, g_act);
    cudaGetSymbolAddress((void**)&p_qhi, g_qhi);
    cudaGetSymbolAddress((void**)&p_qlo, g_qlo);
    cudaGetSymbolAddress((void**)&p_kh, g_kh);
    cudaGetSymbolAddress((void**)&p_vt, g_vt);
    cudaGetSymbolAddress((void**)&p_wq, g_wq);
    cudaGetSymbolAddress((void**)&p_wk, g_wk);
    cudaGetSymbolAddress((void**)&p_wv, g_wv);
    cudaGetSymbolAddress((void**)&p_wo, g_wo);
    cudaGetSymbolAddress((void**)&p_wg, g_wg);
    cudaGetSymbolAddress((void**)&p_wu, g_wu);
    cudaGetSymbolAddress((void**)&p_wd, g_wd);

    cudaFuncSetAttribute(flash_tc, cudaFuncAttributeMaxDynamicSharedMemorySize,
                         FLASH_DSMEM);
    cudaFuncSetAttribute(tngemm<0>, cudaFuncAttributeMaxDynamicSharedMemorySize,
                         GEMM_DSMEM);
    cudaFuncSetAttribute(tngemm<1>, cudaFuncAttributeMaxDynamicSharedMemorySize,
                         GEMM_DSMEM);
    cudaFuncSetAttribute(tngemm<2>, cudaFuncAttributeMaxDynamicSharedMemorySize,
                         GEMM_DSMEM);

    dim3 cb(32, 8);
    // convert grids: (N/32, K/64)
    convert_w<<<dim3(HDIM / 32, HDIM / 64), cb>>>(wq, p_wq, HDIM, HDIM);
    convert_w<<<dim3(HDIM / 32, HDIM / 64), cb>>>(wk, p_wk, HDIM, HDIM);
    convert_w<<<dim3(HDIM / 32, HDIM / 64), cb>>>(wv, p_wv, HDIM, HDIM);
    convert_w<<<dim3(HDIM / 32, HDIM / 64), cb>>>(wo, p_wo, HDIM, HDIM);
    convert_w<<<dim3(IDIM / 32, HDIM / 64), cb>>>(w_gate, p_wg, HDIM, IDIM);
    convert_w<<<dim3(IDIM / 32, HDIM / 64), cb>>>(w_up, p_wu, HDIM, IDIM);
    convert_w<<<dim3(HDIM / 32, IDIM / 64), cb>>>(w_down, p_wd, IDIM, HDIM);

    dim3 gH(SQ / TM, HDIM / TN);   // (16, 32)
    dim3 gI(SQ / TM, IDIM / TN);   // (16, 86)

    // 1. pre-attn RMSNorm -> fp16
    rmsnorm_f16<<<SQ, 256>>>(hidden, ln0, p_act);
    // 2. QKV projections
    tngemm<0><<<gH, 256, GEMM_DSMEM>>>(p_act, p_wq, p_qbuf, nullptr, HDIM, HDIM);
    tngemm<0><<<gH, 256, GEMM_DSMEM>>>(p_act, p_wk, p_kbuf, nullptr, HDIM, HDIM);
    tngemm<2><<<gH, 256, GEMM_DSMEM>>>(p_act, p_wv, out_v, nullptr, HDIM, HDIM);
    // 3. RoPE -> fp16 q (split) / k (single) + fp32 k output; V transpose
    rope_split<<<dim3(SQ, NH), 64>>>(cosC, sinC, p_qbuf, p_kbuf,
                                     p_qhi, p_qlo, p_kh, out_k);
    vtrans<<<dim3(SQ / 32, DH / 32, NH), cb>>>(out_v, p_vt);
    // 4. causal flash attention (fp16 tensor cores) -> fp16 act
    flash_tc<<<dim3(SQ / 128, NH), 256, FLASH_DSMEM>>>(p_qhi, p_qlo, p_kh, p_vt,
                                                       p_act);
    // 5. output projection + residual
    tngemm<1><<<gH, 256, GEMM_DSMEM>>>(p_act, p_wo, p_hid2, hidden, HDIM, HDIM);
    // 6. post-attn RMSNorm -> fp16
    rmsnorm_f16<<<SQ, 256>>>(p_hid2, ln1, p_act);
    // 7. MLP gate / up
    tngemm<0><<<gI, 256, GEMM_DSMEM>>>(p_act, p_wg, p_gate, nullptr, HDIM, IDIM);
    tngemm<0><<<gI, 256, GEMM_DSMEM>>>(p_act, p_wu, p_up, nullptr, HDIM, IDIM);
    // 8. SwiGLU -> fp16
    swiglu_f16<<<(int)(((size_t)SQ * IDIM / 4 + 255) / 256), 256>>>(p_act);
    // 9. down projection + residual -> hidden output
    tngemm<1><<<gH, 256, GEMM_DSMEM>>>(p_act, p_wd, out_h, p_hid2, IDIM, HDIM);
}